// round 4
// baseline (speedup 1.0000x reference)
#include <cuda_runtime.h>
#include <cstdint>
#include <cstddef>

#define D_IN 512
#define DH   32
#define NC   40
#define MAXN 100000
#define MAXE 3200000
#define SCAN_CHUNK 1024
#define MAXBLKS 128   // >= ceil(MAXN/1024) = 98

// ---------------- device scratch (static allocation only) ----------------
// NOTE: referenced ONLY from device code — never passed as kernel args from host.
__device__ __align__(128) int   g_deg[MAXN];
__device__ __align__(128) int   g_rp[MAXN + 1];
__device__ __align__(128) int   g_cursor[MAXN];
__device__ __align__(128) float g_dinv[MAXN];
__device__ __align__(128) int   g_csr[MAXE];
__device__ __align__(128) float g_bufA[(size_t)MAXN * DH];   // g (scaled features)
__device__ __align__(128) float g_bufB[(size_t)MAXN * DH];   // conv output (pre-pairnorm)
__device__ __align__(128) float g_gf[(size_t)MAXN * NC];     // final-layer scaled features
__device__ int   g_bsum[MAXBLKS];
__device__ int   g_boff[MAXBLKS];
__device__ float g_stats[DH + 1];   // [0..31] column sums, [32] total sum of squares
__device__ int   g_is64;

// ---------------- edge dtype detection ----------------
// If edge_index is int64 (little-endian, ids < 2^31), every odd 32-bit word is 0.
// If int32, odd words are random node ids; P(32 consecutive zeros) ~ 0.
__global__ void k_detect(const int* __restrict__ p) {
    int v = p[2 * threadIdx.x + 1];
    unsigned any = __ballot_sync(0xffffffffu, v != 0);
    if (threadIdx.x == 0) g_is64 = (any == 0) ? 1 : 0;
}

__device__ __forceinline__ void load_edge(const void* ei, int E, int e, int& src, int& dst) {
    if (g_is64) {
        const long long* p = (const long long*)ei;
        src = (int)p[e];
        dst = (int)p[(size_t)E + e];
    } else {
        const int* p = (const int*)ei;
        src = p[e];
        dst = p[E + e];
    }
}

// ---------------- CSR construction ----------------
__global__ void k_init(int N) {
    int i = blockIdx.x * blockDim.x + threadIdx.x;
    if (i < N) g_deg[i] = 0;
}

__global__ void k_count(const void* __restrict__ ei, int E) {
    int e = blockIdx.x * blockDim.x + threadIdx.x;
    if (e < E) {
        int src, dst;
        load_edge(ei, E, e, src, dst);
        atomicAdd(&g_deg[dst], 1);
    }
}

// per-1024-chunk block sums
__global__ void k_scan_a(int N) {
    __shared__ int sm[256];
    int blk = blockIdx.x, tid = threadIdx.x;
    int base = blk * SCAN_CHUNK + tid * 4;
    int s = 0;
#pragma unroll
    for (int j = 0; j < 4; j++) {
        int i = base + j;
        if (i < N) s += g_deg[i];
    }
    sm[tid] = s;
    __syncthreads();
    for (int off = 128; off > 0; off >>= 1) {
        if (tid < off) sm[tid] += sm[tid + off];
        __syncthreads();
    }
    if (tid == 0) g_bsum[blk] = sm[0];
}

// scan the (<=128) block sums
__global__ void k_scan_b(int NB) {
    __shared__ int sm[128];
    int t = threadIdx.x;
    int v = (t < NB) ? g_bsum[t] : 0;
    sm[t] = v;
    __syncthreads();
    for (int off = 1; off < 128; off <<= 1) {
        int add = (t >= off) ? sm[t - off] : 0;
        __syncthreads();
        sm[t] += add;
        __syncthreads();
    }
    if (t < NB) g_boff[t] = sm[t] - v;   // exclusive
}

// final scan: row_ptr, cursor, dinv (deg + self loop)
__global__ void k_scan_c(int N) {
    __shared__ int sm[256];
    int blk = blockIdx.x, tid = threadIdx.x;
    int base = blk * SCAN_CHUNK + tid * 4;
    int d[4];
    int s = 0;
#pragma unroll
    for (int j = 0; j < 4; j++) {
        int i = base + j;
        d[j] = (i < N) ? g_deg[i] : 0;
        s += d[j];
    }
    sm[tid] = s;
    __syncthreads();
    int own = s;
    for (int off = 1; off < 256; off <<= 1) {
        int add = (tid >= off) ? sm[tid - off] : 0;
        __syncthreads();
        sm[tid] += add;
        __syncthreads();
    }
    int excl = sm[tid] - own + g_boff[blk];
#pragma unroll
    for (int j = 0; j < 4; j++) {
        int i = base + j;
        if (i < N) {
            g_rp[i] = excl;
            g_cursor[i] = excl;
            g_dinv[i] = rsqrtf((float)(d[j] + 1));   // +1 self loop
            if (i == N - 1) g_rp[N] = excl + d[j];
            excl += d[j];
        }
    }
}

__global__ void k_fill(const void* __restrict__ ei, int E) {
    int e = blockIdx.x * blockDim.x + threadIdx.x;
    if (e < E) {
        int src, dst;
        load_edge(ei, E, e, src, dst);
        int pos = atomicAdd(&g_cursor[dst], 1);
        g_csr[pos] = src;
    }
}

// ---------------- layer-0 GEMM: g_bufA = dinv ⊙ (x @ W0) ----------------
#define BM 256
#define BK 16
__global__ void k_gemm0(const float* __restrict__ x, const float* __restrict__ W, int N) {
    __shared__ float xs[BK][BM + 4];
    __shared__ float ws[BK][DH];
    int tid = threadIdx.x;           // 128 threads
    int ty = tid >> 2;               // 0..31 -> row group *8
    int tx = tid & 3;                // 0..3  -> col group *8
    int rowBase = blockIdx.x * BM;

    float acc[8][8];
#pragma unroll
    for (int i = 0; i < 8; i++)
#pragma unroll
        for (int j = 0; j < 8; j++) acc[i][j] = 0.f;

    for (int k0 = 0; k0 < D_IN; k0 += BK) {
#pragma unroll
        for (int i = 0; i < 8; i++) {
            int idx = tid + i * 128;
            int row = idx >> 2;
            int kq = (idx & 3) << 2;
            float4 v = make_float4(0.f, 0.f, 0.f, 0.f);
            int gr = rowBase + row;
            if (gr < N) v = *(const float4*)(x + (size_t)gr * D_IN + k0 + kq);
            xs[kq + 0][row] = v.x;
            xs[kq + 1][row] = v.y;
            xs[kq + 2][row] = v.z;
            xs[kq + 3][row] = v.w;
        }
        {
            int kk = tid >> 3;
            int nq = (tid & 7) << 2;
            float4 wv = *(const float4*)(W + (size_t)(k0 + kk) * DH + nq);
            ws[kk][nq + 0] = wv.x;
            ws[kk][nq + 1] = wv.y;
            ws[kk][nq + 2] = wv.z;
            ws[kk][nq + 3] = wv.w;
        }
        __syncthreads();
#pragma unroll
        for (int kk = 0; kk < BK; kk++) {
            float a[8], b[8];
#pragma unroll
            for (int i = 0; i < 8; i++) a[i] = xs[kk][ty * 8 + i];
#pragma unroll
            for (int j = 0; j < 8; j++) b[j] = ws[kk][tx * 8 + j];
#pragma unroll
            for (int i = 0; i < 8; i++)
#pragma unroll
                for (int j = 0; j < 8; j++) acc[i][j] = fmaf(a[i], b[j], acc[i][j]);
        }
        __syncthreads();
    }
#pragma unroll
    for (int i = 0; i < 8; i++) {
        int r = rowBase + ty * 8 + i;
        if (r < N) {
            float dv = g_dinv[r];
#pragma unroll
            for (int j = 0; j < 8; j++)
                g_bufA[(size_t)r * DH + tx * 8 + j] = acc[i][j] * dv;
        }
    }
}

// ---------------- propagation, D=32: bufB = dinv*(sum_{src} bufA[src] + bufA[self]) + b ---
__global__ void k_prop32(const float* __restrict__ b, int N) {
    int gt = blockIdx.x * blockDim.x + threadIdx.x;
    if (gt < DH + 1) g_stats[gt] = 0.f;     // zero stats for the next stats kernel
    int lane = threadIdx.x & 31;
    int w = gt >> 5;
    if (w >= N) return;

    const float* g = g_bufA;
    float acc = g[(size_t)w * DH + lane];   // self loop term
    int beg = g_rp[w], end = g_rp[w + 1];
    for (int e0 = beg; e0 < end; e0 += 32) {
        int rem = end - e0;
        int n = rem < 32 ? rem : 32;
        int s = (lane < n) ? g_csr[e0 + lane] : 0;
        int t = 0;
        for (; t + 4 <= n; t += 4) {
            int s0 = __shfl_sync(0xffffffffu, s, t);
            int s1 = __shfl_sync(0xffffffffu, s, t + 1);
            int s2 = __shfl_sync(0xffffffffu, s, t + 2);
            int s3 = __shfl_sync(0xffffffffu, s, t + 3);
            float v0 = g[(size_t)s0 * DH + lane];
            float v1 = g[(size_t)s1 * DH + lane];
            float v2 = g[(size_t)s2 * DH + lane];
            float v3 = g[(size_t)s3 * DH + lane];
            acc += v0; acc += v1; acc += v2; acc += v3;
        }
        for (; t < n; t++) {
            int ss = __shfl_sync(0xffffffffu, s, t);
            acc += g[(size_t)ss * DH + lane];
        }
    }
    g_bufB[(size_t)w * DH + lane] = g_dinv[w] * acc + b[lane];
}

// ---------------- pairnorm stats on bufB: column sums + total sumsq ----------------
__global__ void k_stats(int N) {
    int lane = threadIdx.x & 31;
    int warp = (blockIdx.x * blockDim.x + threadIdx.x) >> 5;
    int nw = (gridDim.x * blockDim.x) >> 5;
    float cs = 0.f, ss = 0.f;
    for (int n = warp; n < N; n += nw) {
        float v = g_bufB[(size_t)n * DH + lane];
        cs += v;
        ss += v * v;
    }
#pragma unroll
    for (int off = 16; off; off >>= 1) ss += __shfl_xor_sync(0xffffffffu, ss, off);
    atomicAdd(&g_stats[lane], cs);
    if (lane == 0) atomicAdd(&g_stats[DH], ss);
}

// ---- fused pairnorm + relu + (t @ W1) + dinv scale (32 -> 32): bufB -> bufA ----
__global__ void k_transform(const float* __restrict__ Wmat, int N, float invN) {
    __shared__ float ws[DH * DH];
    int tid = threadIdx.x, lane = tid & 31;
    for (int i = tid; i < DH * DH; i += blockDim.x) ws[i] = Wmat[i];
    __syncthreads();

    float mu = g_stats[lane] * invN;
    float m2 = mu * mu;
#pragma unroll
    for (int off = 16; off; off >>= 1) m2 += __shfl_xor_sync(0xffffffffu, m2, off);
    float scale = rsqrtf(1e-5f + g_stats[DH] * invN - m2);

    int warp0 = (blockIdx.x * blockDim.x + tid) >> 5;
    int nw = (gridDim.x * blockDim.x) >> 5;
    for (int n = warp0; n < N; n += nw) {
        float t = (g_bufB[(size_t)n * DH + lane] - mu) * scale;
        t = fmaxf(t, 0.f);
        float acc = 0.f;
#pragma unroll
        for (int j = 0; j < DH; j++) {
            float tj = __shfl_sync(0xffffffffu, t, j);
            acc = fmaf(tj, ws[j * DH + lane], acc);
        }
        g_bufA[(size_t)n * DH + lane] = acc * g_dinv[n];
    }
}

// ---- fused pairnorm + relu + (t @ Wf) + dinv scale (32 -> 40): bufB -> g_gf ----
__global__ void k_transformF(const float* __restrict__ Wmat, int N, float invN) {
    __shared__ float ws[DH * NC];
    int tid = threadIdx.x, lane = tid & 31;
    for (int i = tid; i < DH * NC; i += blockDim.x) ws[i] = Wmat[i];
    __syncthreads();

    float mu = g_stats[lane] * invN;
    float m2 = mu * mu;
#pragma unroll
    for (int off = 16; off; off >>= 1) m2 += __shfl_xor_sync(0xffffffffu, m2, off);
    float scale = rsqrtf(1e-5f + g_stats[DH] * invN - m2);

    int warp0 = (blockIdx.x * blockDim.x + tid) >> 5;
    int nw = (gridDim.x * blockDim.x) >> 5;
    int l8 = lane & 7;
    for (int n = warp0; n < N; n += nw) {
        float t = (g_bufB[(size_t)n * DH + lane] - mu) * scale;
        t = fmaxf(t, 0.f);
        float acc0 = 0.f, acc1 = 0.f;
#pragma unroll
        for (int j = 0; j < DH; j++) {
            float tj = __shfl_sync(0xffffffffu, t, j);
            acc0 = fmaf(tj, ws[j * NC + lane], acc0);
            acc1 = fmaf(tj, ws[j * NC + 32 + l8], acc1);
        }
        float dv = g_dinv[n];
        g_gf[(size_t)n * NC + lane] = acc0 * dv;
        if (lane < 8) g_gf[(size_t)n * NC + 32 + lane] = acc1 * dv;
    }
}

// ---------------- final propagation, D=40, writes d_out ----------------
__global__ void k_propF(const float* __restrict__ bf, float* __restrict__ out, int N) {
    int gt = blockIdx.x * blockDim.x + threadIdx.x;
    int lane = threadIdx.x & 31;
    int w = gt >> 5;
    if (w >= N) return;
    int l8 = lane & 7;

    float acc0 = g_gf[(size_t)w * NC + lane];
    float acc1 = g_gf[(size_t)w * NC + 32 + l8];
    int beg = g_rp[w], end = g_rp[w + 1];
    for (int e0 = beg; e0 < end; e0 += 32) {
        int rem = end - e0;
        int n = rem < 32 ? rem : 32;
        int s = (lane < n) ? g_csr[e0 + lane] : 0;
        int t = 0;
        for (; t + 2 <= n; t += 2) {
            int s0 = __shfl_sync(0xffffffffu, s, t);
            int s1 = __shfl_sync(0xffffffffu, s, t + 1);
            float a0 = g_gf[(size_t)s0 * NC + lane];
            float b0 = g_gf[(size_t)s0 * NC + 32 + l8];
            float a1 = g_gf[(size_t)s1 * NC + lane];
            float b1 = g_gf[(size_t)s1 * NC + 32 + l8];
            acc0 += a0; acc1 += b0; acc0 += a1; acc1 += b1;
        }
        for (; t < n; t++) {
            int ss = __shfl_sync(0xffffffffu, s, t);
            acc0 += g_gf[(size_t)ss * NC + lane];
            acc1 += g_gf[(size_t)ss * NC + 32 + l8];
        }
    }
    float dv = g_dinv[w];
    out[(size_t)w * NC + lane] = dv * acc0 + bf[lane];
    if (lane < 8) out[(size_t)w * NC + 32 + lane] = dv * acc1 + bf[32 + lane];
}

// ---------------- host launcher ----------------
extern "C" void kernel_launch(void* const* d_in, const int* in_sizes, int n_in,
                              void* d_out, int out_size) {
    const float* x  = (const float*)d_in[0];
    const void*  ei = d_in[1];
    const float* W0 = (const float*)d_in[2];
    const float* b0 = (const float*)d_in[3];
    const float* W1 = (const float*)d_in[4];
    const float* b1 = (const float*)d_in[5];
    const float* Wf = (const float*)d_in[6];
    const float* bf = (const float*)d_in[7];
    float* out = (float*)d_out;

    int N = in_sizes[0] / D_IN;
    int E = in_sizes[1] / 2;
    float invN = 1.f / (float)N;
    int NB = (N + SCAN_CHUNK - 1) / SCAN_CHUNK;

    // edge dtype detection (int64 vs int32)
    k_detect<<<1, 32>>>((const int*)ei);

    // CSR build
    k_init<<<(N + 255) / 256, 256>>>(N);
    k_count<<<(E + 255) / 256, 256>>>(ei, E);
    k_scan_a<<<NB, 256>>>(N);
    k_scan_b<<<1, 128>>>(NB);
    k_scan_c<<<NB, 256>>>(N);
    k_fill<<<(E + 255) / 256, 256>>>(ei, E);

    // layer 0: dense then propagate
    k_gemm0<<<(N + BM - 1) / BM, 128>>>(x, W0, N);
    k_prop32<<<(N * 32 + 255) / 256, 256>>>(b0, N);
    k_stats<<<1024, 256>>>(N);

    // layer 1
    k_transform<<<592, 256>>>(W1, N, invN);
    k_prop32<<<(N * 32 + 255) / 256, 256>>>(b1, N);
    k_stats<<<1024, 256>>>(N);

    // final layer
    k_transformF<<<592, 256>>>(Wf, N, invN);
    k_propF<<<(N * 32 + 255) / 256, 256>>>(bf, out, N);
}

// round 5
// speedup vs baseline: 1.0276x; 1.0276x over previous
#include <cuda_runtime.h>
#include <cstdint>
#include <cstddef>

#define D_IN 512
#define DH   32
#define NC   40
#define MAXN 100000
#define MAXE 3200000
#define SCAN_CHUNK 1024
#define MAXBLKS 128
#define BM 256
#define BK 16

typedef unsigned long long ull;

// ---------------- device scratch (referenced only from device code) ----------------
__device__ __align__(128) int   g_deg[MAXN];
__device__ __align__(128) int   g_rp[MAXN + 1];
__device__ __align__(128) int   g_cursor[MAXN];
__device__ __align__(128) float g_dinv[MAXN];
__device__ __align__(128) int   g_csr[MAXE];
__device__ __align__(128) int   g_es[MAXE];
__device__ __align__(128) int   g_ed[MAXE];
__device__ __align__(128) float g_bufA[(size_t)MAXN * DH];
__device__ __align__(128) float g_bufB[(size_t)MAXN * DH];
__device__ __align__(128) float g_gf[(size_t)MAXN * NC];
__device__ int   g_bsum[MAXBLKS];
__device__ int   g_boff[MAXBLKS];
__device__ float g_stats[DH + 1];
__device__ int   g_is64;

// ---------------- helpers ----------------
__device__ __forceinline__ void ffma2(ull& d, ull a, ull b) {
    asm("fma.rn.f32x2 %0, %1, %2, %0;" : "+l"(d) : "l"(a), "l"(b));
}
__device__ __forceinline__ ull splat2(float v) {
    unsigned u = __float_as_uint(v);
    return (ull)u | ((ull)u << 32);
}

__device__ __forceinline__ void load_edge(const void* ei, int E, int e, int& src, int& dst) {
    if (g_is64) {
        const long long* p = (const long long*)ei;
        src = (int)p[e];
        dst = (int)p[(size_t)E + e];
    } else {
        const int* p = (const int*)ei;
        src = p[e];
        dst = p[E + e];
    }
}

// ---------------- detect edge dtype + zero degrees ----------------
__global__ void k_detect_init(const int* __restrict__ p, int N) {
    int i = blockIdx.x * blockDim.x + threadIdx.x;
    if (i < N) g_deg[i] = 0;
    if (blockIdx.x == 0 && threadIdx.x < 32) {
        int v = p[2 * threadIdx.x + 1];
        unsigned any = __ballot_sync(0xffffffffu, v != 0);
        if (threadIdx.x == 0) g_is64 = (any == 0) ? 1 : 0;
    }
}

// ---------------- CSR: count degrees + cache int32 edges ----------------
__global__ void k_count(const void* __restrict__ ei, int E) {
    int e = blockIdx.x * blockDim.x + threadIdx.x;
    if (e < E) {
        int src, dst;
        load_edge(ei, E, e, src, dst);
        g_es[e] = src;
        g_ed[e] = dst;
        atomicAdd(&g_deg[dst], 1);
    }
}

__global__ void k_scan_a(int N) {
    __shared__ int sm[256];
    int blk = blockIdx.x, tid = threadIdx.x;
    int base = blk * SCAN_CHUNK + tid * 4;
    int s = 0;
#pragma unroll
    for (int j = 0; j < 4; j++) {
        int i = base + j;
        if (i < N) s += g_deg[i];
    }
    sm[tid] = s;
    __syncthreads();
    for (int off = 128; off > 0; off >>= 1) {
        if (tid < off) sm[tid] += sm[tid + off];
        __syncthreads();
    }
    if (tid == 0) g_bsum[blk] = sm[0];
}

__global__ void k_scan_b(int NB) {
    __shared__ int sm[128];
    int t = threadIdx.x;
    int v = (t < NB) ? g_bsum[t] : 0;
    sm[t] = v;
    __syncthreads();
    for (int off = 1; off < 128; off <<= 1) {
        int add = (t >= off) ? sm[t - off] : 0;
        __syncthreads();
        sm[t] += add;
        __syncthreads();
    }
    if (t < NB) g_boff[t] = sm[t] - v;
}

__global__ void k_scan_c(int N) {
    __shared__ int sm[256];
    int blk = blockIdx.x, tid = threadIdx.x;
    int base = blk * SCAN_CHUNK + tid * 4;
    int d[4];
    int s = 0;
#pragma unroll
    for (int j = 0; j < 4; j++) {
        int i = base + j;
        d[j] = (i < N) ? g_deg[i] : 0;
        s += d[j];
    }
    sm[tid] = s;
    __syncthreads();
    int own = s;
    for (int off = 1; off < 256; off <<= 1) {
        int add = (tid >= off) ? sm[tid - off] : 0;
        __syncthreads();
        sm[tid] += add;
        __syncthreads();
    }
    int excl = sm[tid] - own + g_boff[blk];
#pragma unroll
    for (int j = 0; j < 4; j++) {
        int i = base + j;
        if (i < N) {
            g_rp[i] = excl;
            g_cursor[i] = excl;
            g_dinv[i] = rsqrtf((float)(d[j] + 1));
            if (i == N - 1) g_rp[N] = excl + d[j];
            excl += d[j];
        }
    }
}

__global__ void k_fill(int E) {
    int e = blockIdx.x * blockDim.x + threadIdx.x;
    if (e < E) {
        int dst = g_ed[e];
        int pos = atomicAdd(&g_cursor[dst], 1);
        g_csr[pos] = g_es[e];
    }
}

// ---------------- layer-0 GEMM: g_bufA = dinv ⊙ (x @ W0), f32x2 packed ----------------
__global__ void __launch_bounds__(128) k_gemm0(const float* __restrict__ x,
                                               const float* __restrict__ W, int N) {
    __shared__ float xs[BK][BM + 4];
    __shared__ ull   ws2[BK][DH];          // pre-splatted {w,w} pairs
    int tid = threadIdx.x;
    int ty = tid >> 2;     // 0..31: owns rows ty*8 .. ty*8+7
    int tx = tid & 3;      // 0..3 : owns cols tx*8 .. tx*8+7
    int rowBase = blockIdx.x * BM;

    ull acc2[4][8];        // acc2[ip][j] = rows (2ip, 2ip+1), col j
#pragma unroll
    for (int ip = 0; ip < 4; ip++)
#pragma unroll
        for (int j = 0; j < 8; j++) acc2[ip][j] = 0ull;

    float4 pre[8];
    // prologue: load chunk 0
#pragma unroll
    for (int i = 0; i < 8; i++) {
        int idx = tid + i * 128;
        int row = idx >> 2;
        int kq = (idx & 3) << 2;
        int gr = rowBase + row;
        pre[i] = (gr < N) ? *(const float4*)(x + (size_t)gr * D_IN + kq)
                          : make_float4(0.f, 0.f, 0.f, 0.f);
    }

    for (int k0 = 0; k0 < D_IN; k0 += BK) {
        // commit prefetched x chunk to smem
#pragma unroll
        for (int i = 0; i < 8; i++) {
            int idx = tid + i * 128;
            int row = idx >> 2;
            int kq = (idx & 3) << 2;
            xs[kq + 0][row] = pre[i].x;
            xs[kq + 1][row] = pre[i].y;
            xs[kq + 2][row] = pre[i].z;
            xs[kq + 3][row] = pre[i].w;
        }
        // W chunk -> splatted pairs
        {
            int kk = tid >> 3;
            int nq = (tid & 7) << 2;
            float4 wv = *(const float4*)(W + (size_t)(k0 + kk) * DH + nq);
            ws2[kk][nq + 0] = splat2(wv.x);
            ws2[kk][nq + 1] = splat2(wv.y);
            ws2[kk][nq + 2] = splat2(wv.z);
            ws2[kk][nq + 3] = splat2(wv.w);
        }
        __syncthreads();

        // prefetch next x chunk into registers (overlaps with compute)
        if (k0 + BK < D_IN) {
#pragma unroll
            for (int i = 0; i < 8; i++) {
                int idx = tid + i * 128;
                int row = idx >> 2;
                int kq = (idx & 3) << 2;
                int gr = rowBase + row;
                pre[i] = (gr < N) ? *(const float4*)(x + (size_t)gr * D_IN + k0 + BK + kq)
                                  : make_float4(0.f, 0.f, 0.f, 0.f);
            }
        }

#pragma unroll
        for (int kk = 0; kk < BK; kk++) {
            ull ap[4];
#pragma unroll
            for (int ip = 0; ip < 4; ip++)
                ap[ip] = *(const ull*)&xs[kk][ty * 8 + 2 * ip];
#pragma unroll
            for (int j = 0; j < 8; j++) {
                ull bs = ws2[kk][tx * 8 + j];
#pragma unroll
                for (int ip = 0; ip < 4; ip++) ffma2(acc2[ip][j], ap[ip], bs);
            }
        }
        __syncthreads();
    }

    // epilogue: scale by dinv and store
#pragma unroll
    for (int ip = 0; ip < 4; ip++) {
        int r0 = rowBase + ty * 8 + 2 * ip;
        int r1 = r0 + 1;
        float dv0 = (r0 < N) ? g_dinv[r0] : 0.f;
        float dv1 = (r1 < N) ? g_dinv[r1] : 0.f;
#pragma unroll
        for (int j = 0; j < 8; j++) {
            ull v = acc2[ip][j];
            float lo = __uint_as_float((unsigned)v);
            float hi = __uint_as_float((unsigned)(v >> 32));
            if (r0 < N) g_bufA[(size_t)r0 * DH + tx * 8 + j] = lo * dv0;
            if (r1 < N) g_bufA[(size_t)r1 * DH + tx * 8 + j] = hi * dv1;
        }
    }
}

// ---------------- propagation D=32 (float4, 4 nodes/warp): bufA -> bufB ----------------
__global__ void k_prop32(const float* __restrict__ b, int N) {
    int tid = threadIdx.x;
    if (blockIdx.x == 0 && tid < DH + 1) g_stats[tid] = 0.f;   // zero stats for next k_stats
    int lane = tid & 31;
    int l8 = lane & 7;
    int g8 = lane >> 3;
    int gwarp = (blockIdx.x * blockDim.x + tid) >> 5;
    int w = gwarp * 4 + g8;
    bool alive = (w < N);
    int wc = alive ? w : 0;

    float4 acc = *(const float4*)(g_bufA + (size_t)wc * DH + l8 * 4);  // self loop
    int beg = g_rp[wc];
    int deg = g_rp[wc + 1] - beg;
    if (!alive) deg = 0;

    int mx = deg;
    mx = max(mx, __shfl_xor_sync(0xffffffffu, mx, 16));
    mx = max(mx, __shfl_xor_sync(0xffffffffu, mx, 8));

    for (int t0 = 0; t0 < mx; t0 += 8) {
        int n = deg - t0;                         // per-group remaining
        int s = (l8 < n) ? g_csr[beg + t0 + l8] : 0;
#pragma unroll
        for (int k = 0; k < 8; k++) {
            int sk = __shfl_sync(0xffffffffu, s, k, 8);
            if (k < n) {
                float4 v = *(const float4*)(g_bufA + (size_t)sk * DH + l8 * 4);
                acc.x += v.x; acc.y += v.y; acc.z += v.z; acc.w += v.w;
            }
        }
    }
    if (alive) {
        float dv = g_dinv[w];
        float4 bb = *(const float4*)(b + l8 * 4);
        float4 o;
        o.x = dv * acc.x + bb.x;
        o.y = dv * acc.y + bb.y;
        o.z = dv * acc.z + bb.z;
        o.w = dv * acc.w + bb.w;
        *(float4*)(g_bufB + (size_t)w * DH + l8 * 4) = o;
    }
}

// ---------------- pairnorm stats on bufB ----------------
__global__ void k_stats(int N) {
    int lane = threadIdx.x & 31;
    int warp = (blockIdx.x * blockDim.x + threadIdx.x) >> 5;
    int nw = (gridDim.x * blockDim.x) >> 5;
    float cs = 0.f, ss = 0.f;
    for (int n = warp; n < N; n += nw) {
        float v = g_bufB[(size_t)n * DH + lane];
        cs += v;
        ss += v * v;
    }
#pragma unroll
    for (int off = 16; off; off >>= 1) ss += __shfl_xor_sync(0xffffffffu, ss, off);
    atomicAdd(&g_stats[lane], cs);
    if (lane == 0) atomicAdd(&g_stats[DH], ss);
}

// ---- fused pairnorm + relu + (t @ W1) + dinv scale: bufB -> bufA ----
__global__ void k_transform(const float* __restrict__ Wmat, int N, float invN) {
    __shared__ float ws[DH * DH];
    int tid = threadIdx.x, lane = tid & 31;
    for (int i = tid; i < DH * DH; i += blockDim.x) ws[i] = Wmat[i];
    __syncthreads();

    float mu = g_stats[lane] * invN;
    float m2 = mu * mu;
#pragma unroll
    for (int off = 16; off; off >>= 1) m2 += __shfl_xor_sync(0xffffffffu, m2, off);
    float scale = rsqrtf(1e-5f + g_stats[DH] * invN - m2);

    int warp0 = (blockIdx.x * blockDim.x + tid) >> 5;
    int nw = (gridDim.x * blockDim.x) >> 5;
    for (int n = warp0; n < N; n += nw) {
        float t = (g_bufB[(size_t)n * DH + lane] - mu) * scale;
        t = fmaxf(t, 0.f);
        float acc = 0.f;
#pragma unroll
        for (int j = 0; j < DH; j++) {
            float tj = __shfl_sync(0xffffffffu, t, j);
            acc = fmaf(tj, ws[j * DH + lane], acc);
        }
        g_bufA[(size_t)n * DH + lane] = acc * g_dinv[n];
    }
}

// ---- fused pairnorm + relu + (t @ Wf) + dinv scale: bufB -> g_gf ----
__global__ void k_transformF(const float* __restrict__ Wmat, int N, float invN) {
    __shared__ float ws[DH * NC];
    int tid = threadIdx.x, lane = tid & 31;
    for (int i = tid; i < DH * NC; i += blockDim.x) ws[i] = Wmat[i];
    __syncthreads();

    float mu = g_stats[lane] * invN;
    float m2 = mu * mu;
#pragma unroll
    for (int off = 16; off; off >>= 1) m2 += __shfl_xor_sync(0xffffffffu, m2, off);
    float scale = rsqrtf(1e-5f + g_stats[DH] * invN - m2);

    int warp0 = (blockIdx.x * blockDim.x + tid) >> 5;
    int nw = (gridDim.x * blockDim.x) >> 5;
    int l8 = lane & 7;
    for (int n = warp0; n < N; n += nw) {
        float t = (g_bufB[(size_t)n * DH + lane] - mu) * scale;
        t = fmaxf(t, 0.f);
        float acc0 = 0.f, acc1 = 0.f;
#pragma unroll
        for (int j = 0; j < DH; j++) {
            float tj = __shfl_sync(0xffffffffu, t, j);
            acc0 = fmaf(tj, ws[j * NC + lane], acc0);
            acc1 = fmaf(tj, ws[j * NC + 32 + l8], acc1);
        }
        float dv = g_dinv[n];
        g_gf[(size_t)n * NC + lane] = acc0 * dv;
        if (lane < 8) g_gf[(size_t)n * NC + 32 + lane] = acc1 * dv;
    }
}

// ---------------- final propagation D=40 (float4+float, 4 nodes/warp) -> d_out --------
__global__ void k_propF(const float* __restrict__ bf, float* __restrict__ out, int N) {
    int tid = threadIdx.x;
    int lane = tid & 31;
    int l8 = lane & 7;
    int g8 = lane >> 3;
    int gwarp = (blockIdx.x * blockDim.x + tid) >> 5;
    int w = gwarp * 4 + g8;
    bool alive = (w < N);
    int wc = alive ? w : 0;

    float4 acc = *(const float4*)(g_gf + (size_t)wc * NC + l8 * 4);    // cols 0..31
    float  acc1 = g_gf[(size_t)wc * NC + 32 + l8];                     // cols 32..39
    int beg = g_rp[wc];
    int deg = g_rp[wc + 1] - beg;
    if (!alive) deg = 0;

    int mx = deg;
    mx = max(mx, __shfl_xor_sync(0xffffffffu, mx, 16));
    mx = max(mx, __shfl_xor_sync(0xffffffffu, mx, 8));

    for (int t0 = 0; t0 < mx; t0 += 8) {
        int n = deg - t0;
        int s = (l8 < n) ? g_csr[beg + t0 + l8] : 0;
#pragma unroll
        for (int k = 0; k < 8; k++) {
            int sk = __shfl_sync(0xffffffffu, s, k, 8);
            if (k < n) {
                const float* row = g_gf + (size_t)sk * NC;
                float4 v = *(const float4*)(row + l8 * 4);
                float v1 = row[32 + l8];
                acc.x += v.x; acc.y += v.y; acc.z += v.z; acc.w += v.w;
                acc1 += v1;
            }
        }
    }
    if (alive) {
        float dv = g_dinv[w];
        float4 bb = *(const float4*)(bf + l8 * 4);
        float b1 = bf[32 + l8];
        float4 o;
        o.x = dv * acc.x + bb.x;
        o.y = dv * acc.y + bb.y;
        o.z = dv * acc.z + bb.z;
        o.w = dv * acc.w + bb.w;
        *(float4*)(out + (size_t)w * NC + l8 * 4) = o;
        out[(size_t)w * NC + 32 + l8] = dv * acc1 + b1;
    }
}

// ---------------- host launcher ----------------
extern "C" void kernel_launch(void* const* d_in, const int* in_sizes, int n_in,
                              void* d_out, int out_size) {
    const float* x  = (const float*)d_in[0];
    const void*  ei = d_in[1];
    const float* W0 = (const float*)d_in[2];
    const float* b0 = (const float*)d_in[3];
    const float* W1 = (const float*)d_in[4];
    const float* b1 = (const float*)d_in[5];
    const float* Wf = (const float*)d_in[6];
    const float* bf = (const float*)d_in[7];
    float* out = (float*)d_out;

    int N = in_sizes[0] / D_IN;
    int E = in_sizes[1] / 2;
    float invN = 1.f / (float)N;
    int NB = (N + SCAN_CHUNK - 1) / SCAN_CHUNK;
    int propBlocks = (N + 31) / 32;   // 8 warps/block, 4 nodes/warp

    // CSR build
    k_detect_init<<<(N + 255) / 256, 256>>>((const int*)ei, N);
    k_count<<<(E + 255) / 256, 256>>>(ei, E);
    k_scan_a<<<NB, 256>>>(N);
    k_scan_b<<<1, 128>>>(NB);
    k_scan_c<<<NB, 256>>>(N);
    k_fill<<<(E + 255) / 256, 256>>>(E);

    // layer 0
    k_gemm0<<<(N + BM - 1) / BM, 128>>>(x, W0, N);
    k_prop32<<<propBlocks, 256>>>(b0, N);
    k_stats<<<1024, 256>>>(N);

    // layer 1
    k_transform<<<592, 256>>>(W1, N, invN);
    k_prop32<<<propBlocks, 256>>>(b1, N);
    k_stats<<<1024, 256>>>(N);

    // final layer
    k_transformF<<<592, 256>>>(Wf, N, invN);
    k_propF<<<propBlocks, 256>>>(bf, out, N);
}

// round 7
// speedup vs baseline: 1.2002x; 1.1680x over previous
#include <cuda_runtime.h>
#include <cstdint>
#include <cstddef>

#define D_IN 512
#define DH   32
#define NC   40
#define MAXN 100000
#define MAXE 3200000
#define SCAN_CHUNK 1024
#define MAXBLKS 128
#define BM 256
#define BK 16

// padded smem geometry (conflict-free)
#define XS_G   12            // floats per 8-row group slot (8 data + 4 pad) -> 48B stride
#define XS_ROW (32 * XS_G)   // 384 floats per kk-row
#define WS_T   10            // ulls per tx-group (8 data + 2 pad) -> 80B stride
#define WS_ROW (4 * WS_T)    // 40 ulls per kk-row

typedef unsigned long long ull;

// ---------------- device scratch (referenced only from device code) ----------------
__device__ __align__(128) int   g_deg[MAXN];
__device__ __align__(128) int   g_rp[MAXN + 1];
__device__ __align__(128) int   g_cursor[MAXN];
__device__ __align__(128) float g_dinv[MAXN];
__device__ __align__(128) int   g_csr[MAXE];
__device__ __align__(128) int   g_es[MAXE];
__device__ __align__(128) int   g_ed[MAXE];
__device__ __align__(128) float g_bufA[(size_t)MAXN * DH];
__device__ __align__(128) float g_bufB[(size_t)MAXN * DH];
__device__ __align__(128) float g_gf[(size_t)MAXN * NC];
__device__ int   g_bsum[MAXBLKS];
__device__ int   g_boff[MAXBLKS];
__device__ float g_statsA[DH + 1];
__device__ float g_statsB[DH + 1];
__device__ int   g_is64;

// ---------------- helpers ----------------
__device__ __forceinline__ void ffma2(ull& d, ull a, ull b) {
    asm("fma.rn.f32x2 %0, %1, %2, %0;" : "+l"(d) : "l"(a), "l"(b));
}
__device__ __forceinline__ ull splat2(float v) {
    unsigned u = __float_as_uint(v);
    ull r;
    asm("mov.b64 %0, {%1,%1};" : "=l"(r) : "r"(u));
    return r;
}

__device__ __forceinline__ void load_edge(const void* ei, int E, int e, int& src, int& dst) {
    if (g_is64) {
        const long long* p = (const long long*)ei;
        src = (int)p[e];
        dst = (int)p[(size_t)E + e];
    } else {
        const int* p = (const int*)ei;
        src = p[e];
        dst = p[E + e];
    }
}

// ---------------- detect edge dtype + zero degrees + zero statsA ----------------
__global__ void k_detect_init(const int* __restrict__ p, int N) {
    int i = blockIdx.x * blockDim.x + threadIdx.x;
    if (i < N) g_deg[i] = 0;
    if (blockIdx.x == 0) {
        if (threadIdx.x < DH + 1) g_statsA[threadIdx.x] = 0.f;
        if (threadIdx.x < 32) {
            int v = p[2 * threadIdx.x + 1];
            unsigned any = __ballot_sync(0xffffffffu, v != 0);
            if (threadIdx.x == 0) g_is64 = (any == 0) ? 1 : 0;
        }
    }
}

// ---------------- CSR: count degrees + cache int32 edges ----------------
__global__ void k_count(const void* __restrict__ ei, int E) {
    int e = blockIdx.x * blockDim.x + threadIdx.x;
    if (e < E) {
        int src, dst;
        load_edge(ei, E, e, src, dst);
        g_es[e] = src;
        g_ed[e] = dst;
        atomicAdd(&g_deg[dst], 1);
    }
}

__global__ void k_scan_a(int N) {
    __shared__ int sm[256];
    int blk = blockIdx.x, tid = threadIdx.x;
    int base = blk * SCAN_CHUNK + tid * 4;
    int s = 0;
#pragma unroll
    for (int j = 0; j < 4; j++) {
        int i = base + j;
        if (i < N) s += g_deg[i];
    }
    sm[tid] = s;
    __syncthreads();
    for (int off = 128; off > 0; off >>= 1) {
        if (tid < off) sm[tid] += sm[tid + off];
        __syncthreads();
    }
    if (tid == 0) g_bsum[blk] = sm[0];
}

__global__ void k_scan_b(int NB) {
    __shared__ int sm[128];
    int t = threadIdx.x;
    int v = (t < NB) ? g_bsum[t] : 0;
    sm[t] = v;
    __syncthreads();
    for (int off = 1; off < 128; off <<= 1) {
        int add = (t >= off) ? sm[t - off] : 0;
        __syncthreads();
        sm[t] += add;
        __syncthreads();
    }
    if (t < NB) g_boff[t] = sm[t] - v;
}

__global__ void k_scan_c(int N) {
    __shared__ int sm[256];
    int blk = blockIdx.x, tid = threadIdx.x;
    int base = blk * SCAN_CHUNK + tid * 4;
    int d[4];
    int s = 0;
#pragma unroll
    for (int j = 0; j < 4; j++) {
        int i = base + j;
        d[j] = (i < N) ? g_deg[i] : 0;
        s += d[j];
    }
    sm[tid] = s;
    __syncthreads();
    int own = s;
    for (int off = 1; off < 256; off <<= 1) {
        int add = (tid >= off) ? sm[tid - off] : 0;
        __syncthreads();
        sm[tid] += add;
        __syncthreads();
    }
    int excl = sm[tid] - own + g_boff[blk];
#pragma unroll
    for (int j = 0; j < 4; j++) {
        int i = base + j;
        if (i < N) {
            g_rp[i] = excl;
            g_cursor[i] = excl;
            g_dinv[i] = rsqrtf((float)(d[j] + 1));
            if (i == N - 1) g_rp[N] = excl + d[j];
            excl += d[j];
        }
    }
}

__global__ void k_fill(int E) {
    int e = blockIdx.x * blockDim.x + threadIdx.x;
    if (e < E) {
        int dst = g_ed[e];
        int pos = atomicAdd(&g_cursor[dst], 1);
        g_csr[pos] = g_es[e];
    }
}

// ---------------- layer-0 GEMM: g_bufA = dinv ⊙ (x @ W0), conflict-free smem ----------
__global__ void __launch_bounds__(128) k_gemm0(const float* __restrict__ x,
                                               const float* __restrict__ W, int N) {
    __shared__ float xs[BK * XS_ROW];    // 24 KB, padded groups
    __shared__ ull   ws2[BK * WS_ROW];   // 5 KB, pre-splatted {w,w} pairs, padded
    int tid = threadIdx.x;
    int ty = tid >> 2;     // 0..31: owns rows ty*8 .. ty*8+7
    int tx = tid & 3;      // 0..3 : owns cols tx*8 .. tx*8+7
    int rowBase = blockIdx.x * BM;

    if (blockIdx.x == 0 && tid < DH + 1) g_statsB[tid] = 0.f;   // zero stats for layer-2

    ull acc2[4][8];        // acc2[ip][j] = rows (2ip, 2ip+1) of this thread's 8, col j
#pragma unroll
    for (int ip = 0; ip < 4; ip++)
#pragma unroll
        for (int j = 0; j < 8; j++) acc2[ip][j] = 0ull;

    float4 pre[8];
#pragma unroll
    for (int i = 0; i < 8; i++) {
        int idx = tid + i * 128;
        int row = idx >> 2;
        int kq = (idx & 3) << 2;
        int gr = rowBase + row;
        pre[i] = (gr < N) ? *(const float4*)(x + (size_t)gr * D_IN + kq)
                          : make_float4(0.f, 0.f, 0.f, 0.f);
    }

    for (int k0 = 0; k0 < D_IN; k0 += BK) {
        // commit prefetched x chunk to padded smem
#pragma unroll
        for (int i = 0; i < 8; i++) {
            int idx = tid + i * 128;
            int row = idx >> 2;
            int kq = (idx & 3) << 2;
            int base = (row >> 3) * XS_G + (row & 7);
            xs[(kq + 0) * XS_ROW + base] = pre[i].x;
            xs[(kq + 1) * XS_ROW + base] = pre[i].y;
            xs[(kq + 2) * XS_ROW + base] = pre[i].z;
            xs[(kq + 3) * XS_ROW + base] = pre[i].w;
        }
        // W chunk -> splatted pairs (padded tx-groups)
        {
            int kk = tid >> 3;
            int nq = (tid & 7) << 2;           // col 0,4,...,28
            float4 wv = *(const float4*)(W + (size_t)(k0 + kk) * DH + nq);
            int pbase = kk * WS_ROW + (nq >> 3) * WS_T + (nq & 7);
            ws2[pbase + 0] = splat2(wv.x);
            ws2[pbase + 1] = splat2(wv.y);
            ws2[pbase + 2] = splat2(wv.z);
            ws2[pbase + 3] = splat2(wv.w);
        }
        __syncthreads();

        if (k0 + BK < D_IN) {
#pragma unroll
            for (int i = 0; i < 8; i++) {
                int idx = tid + i * 128;
                int row = idx >> 2;
                int kq = (idx & 3) << 2;
                int gr = rowBase + row;
                pre[i] = (gr < N) ? *(const float4*)(x + (size_t)gr * D_IN + k0 + BK + kq)
                                  : make_float4(0.f, 0.f, 0.f, 0.f);
            }
        }

#pragma unroll
        for (int kk = 0; kk < BK; kk++) {
            const ull* ar = (const ull*)(xs + kk * XS_ROW + ty * XS_G);
            ull ap0 = ar[0], ap1 = ar[1], ap2 = ar[2], ap3 = ar[3];
            const ull* wr = ws2 + kk * WS_ROW + tx * WS_T;
#pragma unroll
            for (int j = 0; j < 8; j++) {
                ull bs = wr[j];
                ffma2(acc2[0][j], ap0, bs);
                ffma2(acc2[1][j], ap1, bs);
                ffma2(acc2[2][j], ap2, bs);
                ffma2(acc2[3][j], ap3, bs);
            }
        }
        __syncthreads();
    }

#pragma unroll
    for (int ip = 0; ip < 4; ip++) {
        int r0 = rowBase + ty * 8 + 2 * ip;
        int r1 = r0 + 1;
        float dv0 = (r0 < N) ? g_dinv[r0] : 0.f;
        float dv1 = (r1 < N) ? g_dinv[r1] : 0.f;
#pragma unroll
        for (int j = 0; j < 8; j++) {
            ull v = acc2[ip][j];
            float lo = __uint_as_float((unsigned)v);
            float hi = __uint_as_float((unsigned)(v >> 32));
            if (r0 < N) g_bufA[(size_t)r0 * DH + tx * 8 + j] = lo * dv0;
            if (r1 < N) g_bufA[(size_t)r1 * DH + tx * 8 + j] = hi * dv1;
        }
    }
}

// ---- propagation D=32 (float4, 4 nodes/warp) + fused pairnorm stats: bufA -> bufB ----
__global__ void k_prop32(const float* __restrict__ b, int N, int which) {
    __shared__ float s_cs[DH];
    __shared__ float s_ss;
    int tid = threadIdx.x;
    if (tid < DH) s_cs[tid] = 0.f;
    if (tid == DH) s_ss = 0.f;
    __syncthreads();

    int lane = tid & 31;
    int l8 = lane & 7;
    int g8 = lane >> 3;
    int gwarp = (blockIdx.x * blockDim.x + tid) >> 5;
    int w = gwarp * 4 + g8;
    bool alive = (w < N);
    int wc = alive ? w : 0;

    float4 acc = *(const float4*)(g_bufA + (size_t)wc * DH + l8 * 4);  // self loop
    int beg = g_rp[wc];
    int deg = g_rp[wc + 1] - beg;
    if (!alive) deg = 0;

    int mx = deg;
    mx = max(mx, __shfl_xor_sync(0xffffffffu, mx, 16));
    mx = max(mx, __shfl_xor_sync(0xffffffffu, mx, 8));

    for (int t0 = 0; t0 < mx; t0 += 8) {
        int n = deg - t0;
        int s = (l8 < n) ? g_csr[beg + t0 + l8] : 0;
#pragma unroll
        for (int k = 0; k < 8; k++) {
            int sk = __shfl_sync(0xffffffffu, s, k, 8);
            if (k < n) {
                float4 v = *(const float4*)(g_bufA + (size_t)sk * DH + l8 * 4);
                acc.x += v.x; acc.y += v.y; acc.z += v.z; acc.w += v.w;
            }
        }
    }

    float4 o = make_float4(0.f, 0.f, 0.f, 0.f);
    if (alive) {
        float dv = g_dinv[w];
        float4 bb = *(const float4*)(b + l8 * 4);
        o.x = dv * acc.x + bb.x;
        o.y = dv * acc.y + bb.y;
        o.z = dv * acc.z + bb.z;
        o.w = dv * acc.w + bb.w;
        *(float4*)(g_bufB + (size_t)w * DH + l8 * 4) = o;
    }

    // fused pairnorm stats (column sums + total sumsq)
    float ssl = o.x * o.x + o.y * o.y + o.z * o.z + o.w * o.w;
#pragma unroll
    for (int off = 16; off; off >>= 1) ssl += __shfl_xor_sync(0xffffffffu, ssl, off);

    o.x += __shfl_xor_sync(0xffffffffu, o.x, 8);
    o.y += __shfl_xor_sync(0xffffffffu, o.y, 8);
    o.z += __shfl_xor_sync(0xffffffffu, o.z, 8);
    o.w += __shfl_xor_sync(0xffffffffu, o.w, 8);
    o.x += __shfl_xor_sync(0xffffffffu, o.x, 16);
    o.y += __shfl_xor_sync(0xffffffffu, o.y, 16);
    o.z += __shfl_xor_sync(0xffffffffu, o.z, 16);
    o.w += __shfl_xor_sync(0xffffffffu, o.w, 16);
    if (lane < 8) {
        atomicAdd(&s_cs[l8 * 4 + 0], o.x);
        atomicAdd(&s_cs[l8 * 4 + 1], o.y);
        atomicAdd(&s_cs[l8 * 4 + 2], o.z);
        atomicAdd(&s_cs[l8 * 4 + 3], o.w);
    }
    if (lane == 0) atomicAdd(&s_ss, ssl);
    __syncthreads();

    float* st = which ? g_statsB : g_statsA;
    if (tid < DH) atomicAdd(&st[tid], s_cs[tid]);
    if (tid == DH) atomicAdd(&st[DH], s_ss);
}

// ---- fused pairnorm + relu + (t @ W1) + dinv scale: bufB -> bufA (stats A) ----
__global__ void k_transform(const float* __restrict__ Wmat, int N, float invN) {
    __shared__ float ws[DH * DH];
    int tid = threadIdx.x, lane = tid & 31;
    for (int i = tid; i < DH * DH; i += blockDim.x) ws[i] = Wmat[i];
    __syncthreads();

    float mu = g_statsA[lane] * invN;
    float m2 = mu * mu;
#pragma unroll
    for (int off = 16; off; off >>= 1) m2 += __shfl_xor_sync(0xffffffffu, m2, off);
    float scale = rsqrtf(1e-5f + g_statsA[DH] * invN - m2);

    int warp0 = (blockIdx.x * blockDim.x + tid) >> 5;
    int nw = (gridDim.x * blockDim.x) >> 5;
    for (int n = warp0; n < N; n += nw) {
        float t = (g_bufB[(size_t)n * DH + lane] - mu) * scale;
        t = fmaxf(t, 0.f);
        float acc = 0.f;
#pragma unroll
        for (int j = 0; j < DH; j++) {
            float tj = __shfl_sync(0xffffffffu, t, j);
            acc = fmaf(tj, ws[j * DH + lane], acc);
        }
        g_bufA[(size_t)n * DH + lane] = acc * g_dinv[n];
    }
}

// ---- fused pairnorm + relu + (t @ Wf) + dinv scale: bufB -> g_gf (stats B) ----
__global__ void k_transformF(const float* __restrict__ Wmat, int N, float invN) {
    __shared__ float ws[DH * NC];
    int tid = threadIdx.x, lane = tid & 31;
    for (int i = tid; i < DH * NC; i += blockDim.x) ws[i] = Wmat[i];
    __syncthreads();

    float mu = g_statsB[lane] * invN;
    float m2 = mu * mu;
#pragma unroll
    for (int off = 16; off; off >>= 1) m2 += __shfl_xor_sync(0xffffffffu, m2, off);
    float scale = rsqrtf(1e-5f + g_statsB[DH] * invN - m2);

    int warp0 = (blockIdx.x * blockDim.x + tid) >> 5;
    int nw = (gridDim.x * blockDim.x) >> 5;
    int l8 = lane & 7;
    for (int n = warp0; n < N; n += nw) {
        float t = (g_bufB[(size_t)n * DH + lane] - mu) * scale;
        t = fmaxf(t, 0.f);
        float acc0 = 0.f, acc1 = 0.f;
#pragma unroll
        for (int j = 0; j < DH; j++) {
            float tj = __shfl_sync(0xffffffffu, t, j);
            acc0 = fmaf(tj, ws[j * NC + lane], acc0);
            acc1 = fmaf(tj, ws[j * NC + 32 + l8], acc1);
        }
        float dv = g_dinv[n];
        g_gf[(size_t)n * NC + lane] = acc0 * dv;
        if (lane < 8) g_gf[(size_t)n * NC + 32 + lane] = acc1 * dv;
    }
}

// ---------------- final propagation D=40 (float4+float, 4 nodes/warp) -> d_out --------
__global__ void k_propF(const float* __restrict__ bf, float* __restrict__ out, int N) {
    int tid = threadIdx.x;
    int lane = tid & 31;
    int l8 = lane & 7;
    int g8 = lane >> 3;
    int gwarp = (blockIdx.x * blockDim.x + tid) >> 5;
    int w = gwarp * 4 + g8;
    bool alive = (w < N);
    int wc = alive ? w : 0;

    float4 acc = *(const float4*)(g_gf + (size_t)wc * NC + l8 * 4);
    float  acc1 = g_gf[(size_t)wc * NC + 32 + l8];
    int beg = g_rp[wc];
    int deg = g_rp[wc + 1] - beg;
    if (!alive) deg = 0;

    int mx = deg;
    mx = max(mx, __shfl_xor_sync(0xffffffffu, mx, 16));
    mx = max(mx, __shfl_xor_sync(0xffffffffu, mx, 8));

    for (int t0 = 0; t0 < mx; t0 += 8) {
        int n = deg - t0;
        int s = (l8 < n) ? g_csr[beg + t0 + l8] : 0;
#pragma unroll
        for (int k = 0; k < 8; k++) {
            int sk = __shfl_sync(0xffffffffu, s, k, 8);
            if (k < n) {
                const float* row = g_gf + (size_t)sk * NC;
                float4 v = *(const float4*)(row + l8 * 4);
                float v1 = row[32 + l8];
                acc.x += v.x; acc.y += v.y; acc.z += v.z; acc.w += v.w;
                acc1 += v1;
            }
        }
    }
    if (alive) {
        float dv = g_dinv[w];
        float4 bb = *(const float4*)(bf + l8 * 4);
        float b1 = bf[32 + l8];
        float4 o;
        o.x = dv * acc.x + bb.x;
        o.y = dv * acc.y + bb.y;
        o.z = dv * acc.z + bb.z;
        o.w = dv * acc.w + bb.w;
        *(float4*)(out + (size_t)w * NC + l8 * 4) = o;
        out[(size_t)w * NC + 32 + l8] = dv * acc1 + b1;
    }
}

// ---------------- host launcher ----------------
extern "C" void kernel_launch(void* const* d_in, const int* in_sizes, int n_in,
                              void* d_out, int out_size) {
    const float* x  = (const float*)d_in[0];
    const void*  ei = d_in[1];
    const float* W0 = (const float*)d_in[2];
    const float* b0 = (const float*)d_in[3];
    const float* W1 = (const float*)d_in[4];
    const float* b1 = (const float*)d_in[5];
    const float* Wf = (const float*)d_in[6];
    const float* bf = (const float*)d_in[7];
    float* out = (float*)d_out;

    int N = in_sizes[0] / D_IN;
    int E = in_sizes[1] / 2;
    float invN = 1.f / (float)N;
    int NB = (N + SCAN_CHUNK - 1) / SCAN_CHUNK;
    int propBlocks = (N + 31) / 32;   // 8 warps/block, 4 nodes/warp

    // CSR build
    k_detect_init<<<(N + 255) / 256, 256>>>((const int*)ei, N);
    k_count<<<(E + 255) / 256, 256>>>(ei, E);
    k_scan_a<<<NB, 256>>>(N);
    k_scan_b<<<1, 128>>>(NB);
    k_scan_c<<<NB, 256>>>(N);
    k_fill<<<(E + 255) / 256, 256>>>(E);

    // layer 0
    k_gemm0<<<(N + BM - 1) / BM, 128>>>(x, W0, N);
    k_prop32<<<propBlocks, 256>>>(b0, N, 0);

    // layer 1
    k_transform<<<592, 256>>>(W1, N, invN);
    k_prop32<<<propBlocks, 256>>>(b1, N, 1);

    // final layer
    k_transformF<<<592, 256>>>(Wf, N, invN);
    k_propF<<<propBlocks, 256>>>(bf, out, N);
}

// round 8
// speedup vs baseline: 1.2847x; 1.0703x over previous
#include <cuda_runtime.h>
#include <cuda_fp16.h>
#include <cstdint>
#include <cstddef>

#define D_IN 512
#define DH   32
#define NC   40
#define MAXN 100000
#define MAXE 3200000
#define SCAN_CHUNK 1024
#define MAXBLKS 128
#define BM 256
#define BK 16

// padded smem geometry (conflict-free)
#define XS_G   12            // floats per 8-row group slot (8 data + 4 pad) -> 48B stride
#define XS_ROW (32 * XS_G)   // 384 floats per kk-row
#define WS_T   10            // ulls per tx-group (8 data + 2 pad) -> 80B stride
#define WS_ROW (4 * WS_T)    // 40 ulls per kk-row

typedef unsigned long long ull;

// ---------------- device scratch (referenced only from device code) ----------------
__device__ __align__(128) int    g_deg[MAXN];
__device__ __align__(128) int    g_rp[MAXN + 1];
__device__ __align__(128) int    g_cursor[MAXN];
__device__ __align__(128) float  g_dinv[MAXN];
__device__ __align__(128) int    g_csr[MAXE];
__device__ __align__(128) int    g_es[MAXE];
__device__ __align__(128) int    g_ed[MAXE];
__device__ __align__(128) __half g_hA[(size_t)MAXN * DH];   // fp16 gathered features (layers 0,1)
__device__ __align__(128) float  g_bufB[(size_t)MAXN * DH]; // fp32 conv output (pre-pairnorm)
__device__ __align__(128) __half g_hgf[(size_t)MAXN * NC];  // fp16 final-layer features
__device__ int   g_bsum[MAXBLKS];
__device__ int   g_boff[MAXBLKS];
__device__ float g_statsA[DH + 1];
__device__ float g_statsB[DH + 1];
__device__ int   g_is64;

// ---------------- helpers ----------------
__device__ __forceinline__ void ffma2(ull& d, ull a, ull b) {
    asm("fma.rn.f32x2 %0, %1, %2, %0;" : "+l"(d) : "l"(a), "l"(b));
}
__device__ __forceinline__ ull splat2(float v) {
    unsigned u = __float_as_uint(v);
    ull r;
    asm("mov.b64 %0, {%1,%1};" : "=l"(r) : "r"(u));
    return r;
}
__device__ __forceinline__ float4 h4_to_f4(uint2 u) {
    __half2 h0 = *reinterpret_cast<__half2*>(&u.x);
    __half2 h1 = *reinterpret_cast<__half2*>(&u.y);
    float2 f0 = __half22float2(h0);
    float2 f1 = __half22float2(h1);
    return make_float4(f0.x, f0.y, f1.x, f1.y);
}

__device__ __forceinline__ void load_edge(const void* ei, int E, int e, int& src, int& dst) {
    if (g_is64) {
        const long long* p = (const long long*)ei;
        src = (int)p[e];
        dst = (int)p[(size_t)E + e];
    } else {
        const int* p = (const int*)ei;
        src = p[e];
        dst = p[E + e];
    }
}

// ---------------- detect edge dtype + zero degrees + zero statsA ----------------
__global__ void k_detect_init(const int* __restrict__ p, int N) {
    int i = blockIdx.x * blockDim.x + threadIdx.x;
    if (i < N) g_deg[i] = 0;
    if (blockIdx.x == 0) {
        if (threadIdx.x < DH + 1) g_statsA[threadIdx.x] = 0.f;
        if (threadIdx.x < 32) {
            int v = p[2 * threadIdx.x + 1];
            unsigned any = __ballot_sync(0xffffffffu, v != 0);
            if (threadIdx.x == 0) g_is64 = (any == 0) ? 1 : 0;
        }
    }
}

// ---------------- CSR: count degrees + cache int32 edges ----------------
__global__ void k_count(const void* __restrict__ ei, int E) {
    int e = blockIdx.x * blockDim.x + threadIdx.x;
    if (e < E) {
        int src, dst;
        load_edge(ei, E, e, src, dst);
        g_es[e] = src;
        g_ed[e] = dst;
        atomicAdd(&g_deg[dst], 1);
    }
}

__global__ void k_scan_a(int N) {
    __shared__ int sm[256];
    int blk = blockIdx.x, tid = threadIdx.x;
    int base = blk * SCAN_CHUNK + tid * 4;
    int s = 0;
#pragma unroll
    for (int j = 0; j < 4; j++) {
        int i = base + j;
        if (i < N) s += g_deg[i];
    }
    sm[tid] = s;
    __syncthreads();
    for (int off = 128; off > 0; off >>= 1) {
        if (tid < off) sm[tid] += sm[tid + off];
        __syncthreads();
    }
    if (tid == 0) g_bsum[blk] = sm[0];
}

__global__ void k_scan_b(int NB) {
    __shared__ int sm[128];
    int t = threadIdx.x;
    int v = (t < NB) ? g_bsum[t] : 0;
    sm[t] = v;
    __syncthreads();
    for (int off = 1; off < 128; off <<= 1) {
        int add = (t >= off) ? sm[t - off] : 0;
        __syncthreads();
        sm[t] += add;
        __syncthreads();
    }
    if (t < NB) g_boff[t] = sm[t] - v;
}

__global__ void k_scan_c(int N) {
    __shared__ int sm[256];
    int blk = blockIdx.x, tid = threadIdx.x;
    int base = blk * SCAN_CHUNK + tid * 4;
    int d[4];
    int s = 0;
#pragma unroll
    for (int j = 0; j < 4; j++) {
        int i = base + j;
        d[j] = (i < N) ? g_deg[i] : 0;
        s += d[j];
    }
    sm[tid] = s;
    __syncthreads();
    int own = s;
    for (int off = 1; off < 256; off <<= 1) {
        int add = (tid >= off) ? sm[tid - off] : 0;
        __syncthreads();
        sm[tid] += add;
        __syncthreads();
    }
    int excl = sm[tid] - own + g_boff[blk];
#pragma unroll
    for (int j = 0; j < 4; j++) {
        int i = base + j;
        if (i < N) {
            g_rp[i] = excl;
            g_cursor[i] = excl;
            g_dinv[i] = rsqrtf((float)(d[j] + 1));
            if (i == N - 1) g_rp[N] = excl + d[j];
            excl += d[j];
        }
    }
}

__global__ void k_fill(int E) {
    int e = blockIdx.x * blockDim.x + threadIdx.x;
    if (e < E) {
        int dst = g_ed[e];
        int pos = atomicAdd(&g_cursor[dst], 1);
        g_csr[pos] = g_es[e];
    }
}

// ---------------- layer-0 GEMM: g_hA = fp16( dinv ⊙ (x @ W0) ), conflict-free smem ------
__global__ void __launch_bounds__(128) k_gemm0(const float* __restrict__ x,
                                               const float* __restrict__ W, int N) {
    __shared__ float xs[BK * XS_ROW];    // 24 KB, padded groups
    __shared__ ull   ws2[BK * WS_ROW];   // 5 KB, pre-splatted {w,w} pairs, padded
    int tid = threadIdx.x;
    int ty = tid >> 2;     // 0..31: owns rows ty*8 .. ty*8+7
    int tx = tid & 3;      // 0..3 : owns cols tx*8 .. tx*8+7
    int rowBase = blockIdx.x * BM;

    if (blockIdx.x == 0 && tid < DH + 1) g_statsB[tid] = 0.f;   // zero stats for layer-2

    ull acc2[4][8];
#pragma unroll
    for (int ip = 0; ip < 4; ip++)
#pragma unroll
        for (int j = 0; j < 8; j++) acc2[ip][j] = 0ull;

    float4 pre[8];
#pragma unroll
    for (int i = 0; i < 8; i++) {
        int idx = tid + i * 128;
        int row = idx >> 2;
        int kq = (idx & 3) << 2;
        int gr = rowBase + row;
        pre[i] = (gr < N) ? *(const float4*)(x + (size_t)gr * D_IN + kq)
                          : make_float4(0.f, 0.f, 0.f, 0.f);
    }

    for (int k0 = 0; k0 < D_IN; k0 += BK) {
#pragma unroll
        for (int i = 0; i < 8; i++) {
            int idx = tid + i * 128;
            int row = idx >> 2;
            int kq = (idx & 3) << 2;
            int base = (row >> 3) * XS_G + (row & 7);
            xs[(kq + 0) * XS_ROW + base] = pre[i].x;
            xs[(kq + 1) * XS_ROW + base] = pre[i].y;
            xs[(kq + 2) * XS_ROW + base] = pre[i].z;
            xs[(kq + 3) * XS_ROW + base] = pre[i].w;
        }
        {
            int kk = tid >> 3;
            int nq = (tid & 7) << 2;
            float4 wv = *(const float4*)(W + (size_t)(k0 + kk) * DH + nq);
            int pbase = kk * WS_ROW + (nq >> 3) * WS_T + (nq & 7);
            ws2[pbase + 0] = splat2(wv.x);
            ws2[pbase + 1] = splat2(wv.y);
            ws2[pbase + 2] = splat2(wv.z);
            ws2[pbase + 3] = splat2(wv.w);
        }
        __syncthreads();

        if (k0 + BK < D_IN) {
#pragma unroll
            for (int i = 0; i < 8; i++) {
                int idx = tid + i * 128;
                int row = idx >> 2;
                int kq = (idx & 3) << 2;
                int gr = rowBase + row;
                pre[i] = (gr < N) ? *(const float4*)(x + (size_t)gr * D_IN + k0 + BK + kq)
                                  : make_float4(0.f, 0.f, 0.f, 0.f);
            }
        }

#pragma unroll
        for (int kk = 0; kk < BK; kk++) {
            const ull* ar = (const ull*)(xs + kk * XS_ROW + ty * XS_G);
            ull ap0 = ar[0], ap1 = ar[1], ap2 = ar[2], ap3 = ar[3];
            const ull* wr = ws2 + kk * WS_ROW + tx * WS_T;
#pragma unroll
            for (int j = 0; j < 8; j++) {
                ull bs = wr[j];
                ffma2(acc2[0][j], ap0, bs);
                ffma2(acc2[1][j], ap1, bs);
                ffma2(acc2[2][j], ap2, bs);
                ffma2(acc2[3][j], ap3, bs);
            }
        }
        __syncthreads();
    }

#pragma unroll
    for (int ip = 0; ip < 4; ip++) {
        int r0 = rowBase + ty * 8 + 2 * ip;
        int r1 = r0 + 1;
        float dv0 = (r0 < N) ? g_dinv[r0] : 0.f;
        float dv1 = (r1 < N) ? g_dinv[r1] : 0.f;
        float v0[8], v1[8];
#pragma unroll
        for (int j = 0; j < 8; j++) {
            ull v = acc2[ip][j];
            v0[j] = __uint_as_float((unsigned)v) * dv0;
            v1[j] = __uint_as_float((unsigned)(v >> 32)) * dv1;
        }
#pragma unroll
        for (int j2 = 0; j2 < 4; j2++) {
            if (r0 < N)
                *(__half2*)(g_hA + (size_t)r0 * DH + tx * 8 + 2 * j2) =
                    __floats2half2_rn(v0[2 * j2], v0[2 * j2 + 1]);
            if (r1 < N)
                *(__half2*)(g_hA + (size_t)r1 * DH + tx * 8 + 2 * j2) =
                    __floats2half2_rn(v1[2 * j2], v1[2 * j2 + 1]);
        }
    }
}

// ---- propagation D=32 fp16 gather (4 nodes/warp) + fused pairnorm stats: hA -> bufB ----
__global__ void k_prop32(const float* __restrict__ b, int N, int which) {
    __shared__ float s_cs[DH];
    __shared__ float s_ss;
    int tid = threadIdx.x;
    if (tid < DH) s_cs[tid] = 0.f;
    if (tid == DH) s_ss = 0.f;
    __syncthreads();

    int lane = tid & 31;
    int l8 = lane & 7;
    int g8 = lane >> 3;
    int gwarp = (blockIdx.x * blockDim.x + tid) >> 5;
    int w = gwarp * 4 + g8;
    bool alive = (w < N);
    int wc = alive ? w : 0;

    uint2 selfu = *((const uint2*)(g_hA + (size_t)wc * DH) + l8);
    float4 acc = h4_to_f4(selfu);                       // self loop
    int beg = g_rp[wc];
    int deg = g_rp[wc + 1] - beg;
    if (!alive) deg = 0;

    int mx = deg;
    mx = max(mx, __shfl_xor_sync(0xffffffffu, mx, 16));
    mx = max(mx, __shfl_xor_sync(0xffffffffu, mx, 8));

    for (int t0 = 0; t0 < mx; t0 += 8) {
        int n = deg - t0;
        int s = (l8 < n) ? g_csr[beg + t0 + l8] : 0;
#pragma unroll
        for (int k = 0; k < 8; k++) {
            int sk = __shfl_sync(0xffffffffu, s, k, 8);
            if (k < n) {
                uint2 u = *((const uint2*)(g_hA + (size_t)sk * DH) + l8);
                float4 v = h4_to_f4(u);
                acc.x += v.x; acc.y += v.y; acc.z += v.z; acc.w += v.w;
            }
        }
    }

    float4 o = make_float4(0.f, 0.f, 0.f, 0.f);
    if (alive) {
        float dv = g_dinv[w];
        float4 bb = *(const float4*)(b + l8 * 4);
        o.x = dv * acc.x + bb.x;
        o.y = dv * acc.y + bb.y;
        o.z = dv * acc.z + bb.z;
        o.w = dv * acc.w + bb.w;
        *(float4*)(g_bufB + (size_t)w * DH + l8 * 4) = o;
    }

    // fused pairnorm stats (column sums + total sumsq)
    float ssl = o.x * o.x + o.y * o.y + o.z * o.z + o.w * o.w;
#pragma unroll
    for (int off = 16; off; off >>= 1) ssl += __shfl_xor_sync(0xffffffffu, ssl, off);

    o.x += __shfl_xor_sync(0xffffffffu, o.x, 8);
    o.y += __shfl_xor_sync(0xffffffffu, o.y, 8);
    o.z += __shfl_xor_sync(0xffffffffu, o.z, 8);
    o.w += __shfl_xor_sync(0xffffffffu, o.w, 8);
    o.x += __shfl_xor_sync(0xffffffffu, o.x, 16);
    o.y += __shfl_xor_sync(0xffffffffu, o.y, 16);
    o.z += __shfl_xor_sync(0xffffffffu, o.z, 16);
    o.w += __shfl_xor_sync(0xffffffffu, o.w, 16);
    if (lane < 8) {
        atomicAdd(&s_cs[l8 * 4 + 0], o.x);
        atomicAdd(&s_cs[l8 * 4 + 1], o.y);
        atomicAdd(&s_cs[l8 * 4 + 2], o.z);
        atomicAdd(&s_cs[l8 * 4 + 3], o.w);
    }
    if (lane == 0) atomicAdd(&s_ss, ssl);
    __syncthreads();

    float* st = which ? g_statsB : g_statsA;
    if (tid < DH) atomicAdd(&st[tid], s_cs[tid]);
    if (tid == DH) atomicAdd(&st[DH], s_ss);
}

// ---- fused pairnorm + relu + (t @ W1) + dinv scale: bufB -> g_hA fp16 (stats A) ----
__global__ void k_transform(const float* __restrict__ Wmat, int N, float invN) {
    __shared__ float ws[DH * DH];
    int tid = threadIdx.x, lane = tid & 31;
    for (int i = tid; i < DH * DH; i += blockDim.x) ws[i] = Wmat[i];
    __syncthreads();

    float mu = g_statsA[lane] * invN;
    float m2 = mu * mu;
#pragma unroll
    for (int off = 16; off; off >>= 1) m2 += __shfl_xor_sync(0xffffffffu, m2, off);
    float scale = rsqrtf(1e-5f + g_statsA[DH] * invN - m2);

    int warp0 = (blockIdx.x * blockDim.x + tid) >> 5;
    int nw = (gridDim.x * blockDim.x) >> 5;
    for (int n = warp0; n < N; n += nw) {
        float t = (g_bufB[(size_t)n * DH + lane] - mu) * scale;
        t = fmaxf(t, 0.f);
        float acc = 0.f;
#pragma unroll
        for (int j = 0; j < DH; j++) {
            float tj = __shfl_sync(0xffffffffu, t, j);
            acc = fmaf(tj, ws[j * DH + lane], acc);
        }
        float val = acc * g_dinv[n];
        float vhi = __shfl_down_sync(0xffffffffu, val, 1);
        if ((lane & 1) == 0)
            *(__half2*)(g_hA + (size_t)n * DH + lane) = __floats2half2_rn(val, vhi);
    }
}

// ---- fused pairnorm + relu + (t @ Wf) + dinv scale: bufB -> g_hgf fp16 (stats B) ----
__global__ void k_transformF(const float* __restrict__ Wmat, int N, float invN) {
    __shared__ float ws[DH * NC];
    int tid = threadIdx.x, lane = tid & 31;
    for (int i = tid; i < DH * NC; i += blockDim.x) ws[i] = Wmat[i];
    __syncthreads();

    float mu = g_statsB[lane] * invN;
    float m2 = mu * mu;
#pragma unroll
    for (int off = 16; off; off >>= 1) m2 += __shfl_xor_sync(0xffffffffu, m2, off);
    float scale = rsqrtf(1e-5f + g_statsB[DH] * invN - m2);

    int warp0 = (blockIdx.x * blockDim.x + tid) >> 5;
    int nw = (gridDim.x * blockDim.x) >> 5;
    int l8 = lane & 7;
    for (int n = warp0; n < N; n += nw) {
        float t = (g_bufB[(size_t)n * DH + lane] - mu) * scale;
        t = fmaxf(t, 0.f);
        float acc0 = 0.f, acc1 = 0.f;
#pragma unroll
        for (int j = 0; j < DH; j++) {
            float tj = __shfl_sync(0xffffffffu, t, j);
            acc0 = fmaf(tj, ws[j * NC + lane], acc0);
            acc1 = fmaf(tj, ws[j * NC + 32 + l8], acc1);
        }
        float dv = g_dinv[n];
        float v0 = acc0 * dv;
        float v0hi = __shfl_down_sync(0xffffffffu, v0, 1);
        if ((lane & 1) == 0)
            *(__half2*)(g_hgf + (size_t)n * NC + lane) = __floats2half2_rn(v0, v0hi);
        float v1 = acc1 * dv;
        float v1hi = __shfl_down_sync(0xffffffffu, v1, 1);
        if (lane < 8 && (lane & 1) == 0)
            *(__half2*)(g_hgf + (size_t)n * NC + 32 + lane) = __floats2half2_rn(v1, v1hi);
    }
}

// ---------------- final propagation D=40 fp16 gather (4 nodes/warp) -> d_out ----------
__global__ void k_propF(const float* __restrict__ bf, float* __restrict__ out, int N) {
    int tid = threadIdx.x;
    int lane = tid & 31;
    int l8 = lane & 7;
    int g8 = lane >> 3;
    int gwarp = (blockIdx.x * blockDim.x + tid) >> 5;
    int w = gwarp * 4 + g8;
    bool alive = (w < N);
    int wc = alive ? w : 0;

    const __half* srow = g_hgf + (size_t)wc * NC;
    float4 acc = h4_to_f4(*((const uint2*)srow + l8));             // cols l8*4..+3
    float2 acc1 = make_float2(0.f, 0.f);                           // cols 32+l8*2, +1 (l8<4)
    if (l8 < 4) {
        unsigned u = *(const unsigned*)(srow + 32 + l8 * 2);
        acc1 = __half22float2(*reinterpret_cast<__half2*>(&u));
    }
    int beg = g_rp[wc];
    int deg = g_rp[wc + 1] - beg;
    if (!alive) deg = 0;

    int mx = deg;
    mx = max(mx, __shfl_xor_sync(0xffffffffu, mx, 16));
    mx = max(mx, __shfl_xor_sync(0xffffffffu, mx, 8));

    for (int t0 = 0; t0 < mx; t0 += 8) {
        int n = deg - t0;
        int s = (l8 < n) ? g_csr[beg + t0 + l8] : 0;
#pragma unroll
        for (int k = 0; k < 8; k++) {
            int sk = __shfl_sync(0xffffffffu, s, k, 8);
            if (k < n) {
                const __half* row = g_hgf + (size_t)sk * NC;
                float4 v = h4_to_f4(*((const uint2*)row + l8));
                acc.x += v.x; acc.y += v.y; acc.z += v.z; acc.w += v.w;
                if (l8 < 4) {
                    unsigned u = *(const unsigned*)(row + 32 + l8 * 2);
                    float2 v1 = __half22float2(*reinterpret_cast<__half2*>(&u));
                    acc1.x += v1.x; acc1.y += v1.y;
                }
            }
        }
    }
    if (alive) {
        float dv = g_dinv[w];
        float4 bb = *(const float4*)(bf + l8 * 4);
        float4 o;
        o.x = dv * acc.x + bb.x;
        o.y = dv * acc.y + bb.y;
        o.z = dv * acc.z + bb.z;
        o.w = dv * acc.w + bb.w;
        *(float4*)(out + (size_t)w * NC + l8 * 4) = o;
        if (l8 < 4) {
            float2 be = *(const float2*)(bf + 32 + l8 * 2);
            float2 o1;
            o1.x = dv * acc1.x + be.x;
            o1.y = dv * acc1.y + be.y;
            *(float2*)(out + (size_t)w * NC + 32 + l8 * 2) = o1;
        }
    }
}

// ---------------- host launcher ----------------
extern "C" void kernel_launch(void* const* d_in, const int* in_sizes, int n_in,
                              void* d_out, int out_size) {
    const float* x  = (const float*)d_in[0];
    const void*  ei = d_in[1];
    const float* W0 = (const float*)d_in[2];
    const float* b0 = (const float*)d_in[3];
    const float* W1 = (const float*)d_in[4];
    const float* b1 = (const float*)d_in[5];
    const float* Wf = (const float*)d_in[6];
    const float* bf = (const float*)d_in[7];
    float* out = (float*)d_out;

    int N = in_sizes[0] / D_IN;
    int E = in_sizes[1] / 2;
    float invN = 1.f / (float)N;
    int NB = (N + SCAN_CHUNK - 1) / SCAN_CHUNK;
    int propBlocks = (N + 31) / 32;   // 8 warps/block, 4 nodes/warp

    // CSR build
    k_detect_init<<<(N + 255) / 256, 256>>>((const int*)ei, N);
    k_count<<<(E + 255) / 256, 256>>>(ei, E);
    k_scan_a<<<NB, 256>>>(N);
    k_scan_b<<<1, 128>>>(NB);
    k_scan_c<<<NB, 256>>>(N);
    k_fill<<<(E + 255) / 256, 256>>>(E);

    // layer 0
    k_gemm0<<<(N + BM - 1) / BM, 128>>>(x, W0, N);
    k_prop32<<<propBlocks, 256>>>(b0, N, 0);

    // layer 1
    k_transform<<<592, 256>>>(W1, N, invN);
    k_prop32<<<propBlocks, 256>>>(b1, N, 1);

    // final layer
    k_transformF<<<592, 256>>>(Wf, N, invN);
    k_propF<<<propBlocks, 256>>>(bf, out, N);
}